// round 6
// baseline (speedup 1.0000x reference)
#include <cuda_runtime.h>
#include <math.h>

#define VOCAB 50257
#define EMB   128
#define VPB   96           // 96 floats = 384 B = 3 full lines, always 128B-aligned
#define GRID  524          // ceil(50257/96); co-resident (524 <= 148*6)

// ---------------- persistent scratch (no allocations allowed) ----------------
__device__ float    g_h[EMB];       // hidden accumulator; zero at load, re-zeroed each run
__device__ float    g_m[GRID];      // per-block logit max
__device__ float    g_z[GRID];      // per-block sum exp(l - m_b)
__device__ unsigned g_barrier = 0;  // monotone arrival counter (reset each run)
__device__ unsigned g_done    = 0;  // completion counter for reset

// ---------------- grid barrier with nanosleep backoff ------------------------
__device__ __forceinline__ void grid_bar(unsigned target) {
    __syncthreads();
    if (threadIdx.x == 0) {
        __threadfence();
        unsigned arrived = atomicAdd(&g_barrier, 1u) + 1u;
        if (arrived < target) {
            volatile unsigned* p = &g_barrier;
            while (*p < target) __nanosleep(64);
        }
        __threadfence();
    }
    __syncthreads();
}

// ---------------- block reductions (fixed order -> deterministic) -----------
__device__ __forceinline__ float blockReduceSum(float v, float* sm) {
    int lane = threadIdx.x & 31, warp = threadIdx.x >> 5;
#pragma unroll
    for (int o = 16; o; o >>= 1) v += __shfl_xor_sync(0xffffffffu, v, o);
    if (lane == 0) sm[warp] = v;
    __syncthreads();
    v = (warp == 0 && lane < 8) ? sm[lane] : 0.f;
    if (warp == 0) {
#pragma unroll
        for (int o = 4; o; o >>= 1) v += __shfl_xor_sync(0xffffffffu, v, o);
    }
    return v;  // valid on thread 0
}

__device__ __forceinline__ float blockReduceMax(float v, float* sm) {
    int lane = threadIdx.x & 31, warp = threadIdx.x >> 5;
#pragma unroll
    for (int o = 16; o; o >>= 1) v = fmaxf(v, __shfl_xor_sync(0xffffffffu, v, o));
    if (lane == 0) sm[warp] = v;
    __syncthreads();
    v = (warp == 0 && lane < 8) ? sm[lane] : -3.402823466e38f;
    if (warp == 0) {
#pragma unroll
        for (int o = 4; o; o >>= 1) v = fmaxf(v, __shfl_xor_sync(0xffffffffu, v, o));
    }
    return v;  // valid on thread 0
}

// ---------------- the single persistent kernel ------------------------------
__global__ void __launch_bounds__(256, 6)
w2v_persist(const float* __restrict__ oh, const float* __restrict__ Wq,
            const float* __restrict__ bq, const float* __restrict__ Ww,
            const float* __restrict__ bw, float* __restrict__ out,
            int rows, float inv_len)
{
    __shared__ float sh_sp[2][VPB];   // per-t-segment column sums
    __shared__ float sh_s[VPB];       // folded column sums for this chunk
    __shared__ float sh_hid[EMB];
    __shared__ float sh_log[VPB];
    __shared__ float sh_red[8];
    __shared__ float sh_bc;

    const int tid = threadIdx.x;
    const int b   = blockIdx.x;
    const int v0  = b * VPB;
    const int cnt = min(VPB, VOCAB - v0);      // 49..96, >0 for all blocks

    // ===== Phase A1: column sums of this block's 96-column chunk of T =====
    // 2 t-segments x 96 columns = 192 active threads; rows split ~100/100.
    {
        const int seg = tid / VPB;             // 0,1 active; 2 idle (tid>=192)
        const int c   = tid - seg * VPB;
        if (seg < 2) {
            float acc = 0.f;
            if (c < cnt) {
                const int rp = (rows + 1) >> 1;
                const int t0 = seg * rp;
                const int t1 = min(rows, t0 + rp);
                const size_t S = (size_t)VOCAB;
                const float* p = oh + (size_t)t0 * S + (v0 + c);
                int n = t1 - t0, i = 0;
                for (; i + 8 <= n; i += 8) {
                    float a0 = p[0*S], a1 = p[1*S], a2 = p[2*S], a3 = p[3*S];
                    float a4 = p[4*S], a5 = p[5*S], a6 = p[6*S], a7 = p[7*S];
                    acc += ((a0 + a1) + (a2 + a3)) + ((a4 + a5) + (a6 + a7));
                    p += 8 * S;
                }
                for (; i < n; ++i) { acc += *p; p += S; }
            }
            sh_sp[seg][c] = acc;
        }
        __syncthreads();
        if (tid < VPB)
            sh_s[tid] = sh_sp[0][tid] + sh_sp[1][tid];
        __syncthreads();
    }

    // ===== Phase A2: this chunk's contribution to hidden; REDG per e =====
    // two threads per e-row; each reads a 192B half of the 384B (3-line) segment
    {
        const int e    = tid >> 1;             // 0..127
        const int half = tid & 1;
        const int clo  = half * 48;
        const int chi  = min(cnt, clo + 48);
        const float* wr = Wq + (size_t)e * VOCAB + v0;
        float acc = 0.f;
#pragma unroll 4
        for (int c = clo; c < chi; ++c)
            acc += sh_s[c] * wr[c];
        acc += __shfl_xor_sync(0xffffffffu, acc, 1);   // pair-fold halves
        if (half == 0) atomicAdd(&g_h[e], acc);
    }
    grid_bar(1u * GRID);

    // ===== Phase B: logits for this block's v-range + (m_b, Z_b) =====
    {
        if (tid < EMB)
            sh_hid[tid] = g_h[tid] * inv_len + bq[tid];
        __syncthreads();

        const int lane = tid & 31, warp = tid >> 5;
        const float4 h4 = reinterpret_cast<const float4*>(sh_hid)[lane];
        float wmax = -3.402823466e38f;
        // two rows in flight per iteration
        for (int k = warp; k < cnt; k += 16) {
            const int k2ok = (k + 8) < cnt;
            const int vA = v0 + k;
            const int vB = v0 + k + (k2ok ? 8 : 0);
            const float4 wA = reinterpret_cast<const float4*>(Ww + (size_t)vA * EMB)[lane];
            const float4 wB = reinterpret_cast<const float4*>(Ww + (size_t)vB * EMB)[lane];
            float pA = wA.x * h4.x + wA.y * h4.y + wA.z * h4.z + wA.w * h4.w;
            float pB = wB.x * h4.x + wB.y * h4.y + wB.z * h4.z + wB.w * h4.w;
#pragma unroll
            for (int o = 16; o; o >>= 1) {
                pA += __shfl_xor_sync(0xffffffffu, pA, o);
                pB += __shfl_xor_sync(0xffffffffu, pB, o);
            }
            const float lgA = pA + __ldg(bw + vA);
            if (lane == 0) sh_log[k] = lgA;
            wmax = fmaxf(wmax, lgA);
            if (k2ok) {
                const float lgB = pB + __ldg(bw + vB);
                if (lane == 0) sh_log[k + 8] = lgB;
                wmax = fmaxf(wmax, lgB);
            }
        }
        if (lane == 0) sh_red[warp] = wmax;
        __syncthreads();
        if (tid == 0) {
            float m = sh_red[0];
#pragma unroll
            for (int i = 1; i < 8; ++i) m = fmaxf(m, sh_red[i]);
            sh_bc = m;
        }
        __syncthreads();
        const float m_b = sh_bc;
        __syncthreads();  // protect sh_red reuse inside blockReduceSum
        float ez = (tid < cnt) ? expf(sh_log[tid] - m_b) : 0.f;
        const float Z = blockReduceSum(ez, sh_red);
        if (tid == 0) { g_m[b] = m_b; g_z[b] = Z; }
    }
    grid_bar(2u * GRID);

    // ===== Phase C: merge (m,Z) -> LSE; write out; restore g_h to zero =====
    {
        if (b == 0 && tid < EMB) g_h[tid] = 0.f;   // all g_h reads done pre-barrier

        float lm = -3.402823466e38f;
        for (int i = tid; i < GRID; i += 256) lm = fmaxf(lm, g_m[i]);
        float M = blockReduceMax(lm, sh_red);
        if (tid == 0) sh_bc = M;
        __syncthreads();
        M = sh_bc;
        __syncthreads();
        float lz = 0.f;
        for (int i = tid; i < GRID; i += 256) lz += g_z[i] * expf(g_m[i] - M);
        const float Z = blockReduceSum(lz, sh_red);
        if (tid == 0) sh_bc = M + logf(Z);
        __syncthreads();
        const float lse = sh_bc;
        if (tid < cnt) out[v0 + tid] = sh_log[tid] - lse;
    }

    // ===== Reset barrier state for next graph replay =====
    __threadfence();
    __syncthreads();
    if (tid == 0) {
        const unsigned old = atomicAdd(&g_done, 1u);
        if (old == GRID - 1u) {        // last block of the whole grid
            g_barrier = 0u;            // nobody spins anymore: all passed barrier 2
            g_done    = 0u;
            __threadfence();
        }
    }
}

// ---------------- launch -----------------------------------------------------
extern "C" void kernel_launch(void* const* d_in, const int* in_sizes, int n_in,
                              void* d_out, int out_size) {
    const float* oh = (const float*)d_in[0];
    // d_in[1] is the scalar `length` (== CTX); rows derived from shape
    const float* Wq = (const float*)d_in[2];
    const float* bq = (const float*)d_in[3];
    const float* Ww = (const float*)d_in[4];
    const float* bw = (const float*)d_in[5];
    float* out = (float*)d_out;

    const int rows = in_sizes[0] / VOCAB;       // 200
    const float inv_len = 1.0f / (float)rows;   // length == CTX here

    w2v_persist<<<GRID, 256>>>(oh, Wq, bq, Ww, bw, out, rows, inv_len);
}

// round 8
// speedup vs baseline: 1.1594x; 1.1594x over previous
#include <cuda_runtime.h>
#include <math.h>

#define VOCAB 50257
#define EMB   128
#define VPB   96           // 96 floats = 384 B = 3 full lines, 128B-aligned chunks
#define GRID  524          // ceil(50257/96); co-resident (524 <= 148*4)

// ---------------- persistent scratch (no allocations allowed) ----------------
__device__ float    g_h[EMB];       // hidden accumulator; zero at load, re-zeroed each run
__device__ float    g_m[GRID];      // per-block logit max
__device__ float    g_z[GRID];      // per-block sum exp(l - m_b)
__device__ unsigned g_barrier = 0;  // monotone arrival counter (reset each run)
__device__ unsigned g_done    = 0;  // completion counter for reset

// ---------------- grid barrier with nanosleep backoff ------------------------
__device__ __forceinline__ void grid_bar(unsigned target) {
    __syncthreads();
    if (threadIdx.x == 0) {
        __threadfence();
        unsigned arrived = atomicAdd(&g_barrier, 1u) + 1u;
        if (arrived < target) {
            volatile unsigned* p = &g_barrier;
            while (*p < target) __nanosleep(64);
        }
        __threadfence();
    }
    __syncthreads();
}

// ---------------- block reductions (fixed order -> deterministic) -----------
__device__ __forceinline__ float blockReduceSum(float v, float* sm) {
    int lane = threadIdx.x & 31, warp = threadIdx.x >> 5;
#pragma unroll
    for (int o = 16; o; o >>= 1) v += __shfl_xor_sync(0xffffffffu, v, o);
    if (lane == 0) sm[warp] = v;
    __syncthreads();
    v = (warp == 0 && lane < 8) ? sm[lane] : 0.f;
    if (warp == 0) {
#pragma unroll
        for (int o = 4; o; o >>= 1) v += __shfl_xor_sync(0xffffffffu, v, o);
    }
    return v;  // valid on thread 0
}

__device__ __forceinline__ float blockReduceMax(float v, float* sm) {
    int lane = threadIdx.x & 31, warp = threadIdx.x >> 5;
#pragma unroll
    for (int o = 16; o; o >>= 1) v = fmaxf(v, __shfl_xor_sync(0xffffffffu, v, o));
    if (lane == 0) sm[warp] = v;
    __syncthreads();
    v = (warp == 0 && lane < 8) ? sm[lane] : -3.402823466e38f;
    if (warp == 0) {
#pragma unroll
        for (int o = 4; o; o >>= 1) v = fmaxf(v, __shfl_xor_sync(0xffffffffu, v, o));
    }
    return v;  // valid on thread 0
}

// ---------------- the single persistent kernel ------------------------------
__global__ void __launch_bounds__(256, 4)
w2v_persist(const float* __restrict__ oh, const float* __restrict__ Wq,
            const float* __restrict__ bq, const float* __restrict__ Ww,
            const float* __restrict__ bw, float* __restrict__ out,
            int rows, float inv_len)
{
    __shared__ float sh_sp[8][VPB];   // per-warp column-sum partials
    __shared__ float sh_s[VPB];       // folded column sums for this chunk
    __shared__ float sh_hid[EMB];
    __shared__ float sh_log[VPB];
    __shared__ float sh_red[8];
    __shared__ float sh_bc;

    const int tid  = threadIdx.x;
    const int lane = tid & 31, warp = tid >> 5;
    const int b    = blockIdx.x;
    const int v0   = b * VPB;
    const int cnt  = min(VPB, VOCAB - v0);     // 49..96, >0 for all blocks

    // ===== Phase A1: column sums; all 8 warps, rows round-robin, MLP=12 =====
    {
        float a0 = 0.f, a1 = 0.f, a2 = 0.f;
        const size_t S = (size_t)VOCAB;
        const float* base = oh + v0;
        if (cnt == VPB) {
            int t = warp;
            for (; t + 24 < rows; t += 32) {          // 4 rows in flight
                const float* p0 = base + (size_t)(t     ) * S;
                const float* p1 = base + (size_t)(t +  8) * S;
                const float* p2 = base + (size_t)(t + 16) * S;
                const float* p3 = base + (size_t)(t + 24) * S;
                float x00 = p0[lane], x01 = p0[lane+32], x02 = p0[lane+64];
                float x10 = p1[lane], x11 = p1[lane+32], x12 = p1[lane+64];
                float x20 = p2[lane], x21 = p2[lane+32], x22 = p2[lane+64];
                float x30 = p3[lane], x31 = p3[lane+32], x32 = p3[lane+64];
                a0 += (x00 + x10) + (x20 + x30);
                a1 += (x01 + x11) + (x21 + x31);
                a2 += (x02 + x12) + (x22 + x32);
            }
            for (; t < rows; t += 8) {
                const float* p = base + (size_t)t * S;
                a0 += p[lane]; a1 += p[lane+32]; a2 += p[lane+64];
            }
        } else {
            const bool ok0 = lane < cnt, ok1 = (lane+32) < cnt, ok2 = (lane+64) < cnt;
            for (int t = warp; t < rows; t += 8) {
                const float* p = base + (size_t)t * S;
                if (ok0) a0 += p[lane];
                if (ok1) a1 += p[lane+32];
                if (ok2) a2 += p[lane+64];
            }
        }
        sh_sp[warp][lane]      = a0;
        sh_sp[warp][lane + 32] = a1;
        sh_sp[warp][lane + 64] = a2;
        __syncthreads();
        if (tid < VPB) {
            float s = 0.f;
#pragma unroll
            for (int w = 0; w < 8; ++w) s += sh_sp[w][tid];
            sh_s[tid] = s;
        }
        __syncthreads();
    }

    // ===== Phase A2: chunk's contribution to hidden; fully unrolled dot =====
    {
        const int e    = tid >> 1;
        const int half = tid & 1;
        const int c0   = half * 48;
        const float* wr = Wq + (size_t)e * VOCAB + v0 + c0;
        float acc = 0.f;
        if (cnt == VPB) {
#pragma unroll
            for (int c = 0; c < 48; ++c) acc += sh_s[c0 + c] * wr[c];
        } else {
            const int hi = min(cnt - c0, 48);
            for (int c = 0; c < hi; ++c) acc += sh_s[c0 + c] * wr[c];
        }
        acc += __shfl_xor_sync(0xffffffffu, acc, 1);   // pair-fold halves
        if (half == 0) atomicAdd(&g_h[e], acc);
    }
    grid_bar(1u * GRID);

    // ===== Phase B: logits; 8 lanes/row x 4 rows/warp, 3-shfl reduce =====
    {
        if (tid < EMB)
            sh_hid[tid] = g_h[tid] * inv_len + bq[tid];
        __syncthreads();

        const int g = (tid >> 3) & 3;    // 8-lane group within warp
        const int l = tid & 7;
        const float4 h0 = reinterpret_cast<const float4*>(sh_hid)[l];
        const float4 h1 = reinterpret_cast<const float4*>(sh_hid)[l +  8];
        const float4 h2 = reinterpret_cast<const float4*>(sh_hid)[l + 16];
        const float4 h3 = reinterpret_cast<const float4*>(sh_hid)[l + 24];
        float wmax = -3.402823466e38f;
#pragma unroll
        for (int j = 0; j < 3; ++j) {
            const int r  = j * 32 + (warp << 2) + g;
            const int rr = min(r, cnt - 1);
            const float4* wrow = reinterpret_cast<const float4*>(Ww + (size_t)(v0 + rr) * EMB);
            const float4 w0 = wrow[l], w1 = wrow[l + 8], w2 = wrow[l + 16], w3 = wrow[l + 24];
            float p = (w0.x*h0.x + w0.y*h0.y + w0.z*h0.z + w0.w*h0.w)
                    + (w1.x*h1.x + w1.y*h1.y + w1.z*h1.z + w1.w*h1.w)
                    + (w2.x*h2.x + w2.y*h2.y + w2.z*h2.z + w2.w*h2.w)
                    + (w3.x*h3.x + w3.y*h3.y + w3.z*h3.z + w3.w*h3.w);
            p += __shfl_xor_sync(0xffffffffu, p, 1);
            p += __shfl_xor_sync(0xffffffffu, p, 2);
            p += __shfl_xor_sync(0xffffffffu, p, 4);
            const float lg = p + __ldg(bw + v0 + rr);
            if (r < cnt) {
                if (l == 0) sh_log[r] = lg;
                wmax = fmaxf(wmax, lg);
            }
        }
        if (lane == 0) sh_red[warp] = wmax;   // lane-level max folded below
        // fold full warp max first
        {
            float wm = wmax;
#pragma unroll
            for (int o = 16; o; o >>= 1) wm = fmaxf(wm, __shfl_xor_sync(0xffffffffu, wm, o));
            if (lane == 0) sh_red[warp] = wm;
        }
        __syncthreads();
        if (tid == 0) {
            float m = sh_red[0];
#pragma unroll
            for (int i = 1; i < 8; ++i) m = fmaxf(m, sh_red[i]);
            sh_bc = m;
        }
        __syncthreads();
        const float m_b = sh_bc;
        __syncthreads();  // protect sh_red reuse inside blockReduceSum
        float ez = (tid < cnt) ? expf(sh_log[tid] - m_b) : 0.f;
        const float Z = blockReduceSum(ez, sh_red);
        if (tid == 0) { g_m[b] = m_b; g_z[b] = Z; }
    }
    grid_bar(2u * GRID);

    // ===== Phase C: merge (m,Z) -> LSE; write out; restore g_h to zero =====
    {
        if (b == 0 && tid < EMB) g_h[tid] = 0.f;   // all g_h reads done pre-barrier

        float lm = -3.402823466e38f;
        for (int i = tid; i < GRID; i += 256) lm = fmaxf(lm, g_m[i]);
        float M = blockReduceMax(lm, sh_red);
        if (tid == 0) sh_bc = M;
        __syncthreads();
        M = sh_bc;
        __syncthreads();
        float lz = 0.f;
        for (int i = tid; i < GRID; i += 256) lz += g_z[i] * expf(g_m[i] - M);
        const float Z = blockReduceSum(lz, sh_red);
        if (tid == 0) sh_bc = M + logf(Z);
        __syncthreads();
        const float lse = sh_bc;
        if (tid < cnt) out[v0 + tid] = sh_log[tid] - lse;
    }

    // ===== Reset barrier state for next graph replay =====
    __threadfence();
    __syncthreads();
    if (tid == 0) {
        const unsigned old = atomicAdd(&g_done, 1u);
        if (old == GRID - 1u) {        // last block of the whole grid
            g_barrier = 0u;            // nobody spins anymore: all passed barrier 2
            g_done    = 0u;
            __threadfence();
        }
    }
}

// ---------------- launch -----------------------------------------------------
extern "C" void kernel_launch(void* const* d_in, const int* in_sizes, int n_in,
                              void* d_out, int out_size) {
    const float* oh = (const float*)d_in[0];
    // d_in[1] is the scalar `length` (== CTX); rows derived from shape
    const float* Wq = (const float*)d_in[2];
    const float* bq = (const float*)d_in[3];
    const float* Ww = (const float*)d_in[4];
    const float* bw = (const float*)d_in[5];
    float* out = (float*)d_out;

    const int rows = in_sizes[0] / VOCAB;       // 200
    const float inv_len = 1.0f / (float)rows;   // length == CTX here

    w2v_persist<<<GRID, 256>>>(oh, Wq, bq, Ww, bw, out, rows, inv_len);
}